// round 4
// baseline (speedup 1.0000x reference)
#include <cuda_runtime.h>
#include <cstdint>

// Problem constants (fixed by the dataset)
#define BB 8
#define CC 32
#define RR 2048
#define II 64
#define OO 64
#define BC (BB*CC)            // 256
#define NCH 8                 // r-chunks per (b,c) in routing
#define CHR (RR/NCH)          // 256 r per chunk

typedef unsigned long long ull;

// -------- scratch (no allocations allowed -> __device__ globals) ----------
__device__ float g_priors[BB*CC*RR*OO];     // 128 MiB: priors[(b*CC+c)][r][o]
__device__ float g_s[BC*OO];                // s per (b,c,o)
__device__ float g_V[BC*OO];                // accumulated v0+v1+...
__device__ float g_pm[BC*NCH*OO];           // partial softmax max
__device__ float g_pl[BC*NCH*OO];           // partial softmax denom
__device__ float g_pw[BC*NCH*OO];           // partial weighted sum
__device__ float g_n2[3];                   // squash norms per iteration

// -------- packed f32x2 helpers (FFMA2 path, PTX-only on sm_103a) ----------
__device__ __forceinline__ ull pack2(float a, float b) {
    ull r;
    asm("mov.b64 %0, {%1, %2};" : "=l"(r)
        : "r"(__float_as_uint(a)), "r"(__float_as_uint(b)));
    return r;
}
__device__ __forceinline__ ull fma2(ull a, ull b, ull c) {
    ull d;
    asm("fma.rn.f32x2 %0, %1, %2, %3;" : "=l"(d) : "l"(a), "l"(b), "l"(c));
    return d;
}
__device__ __forceinline__ float2 unpack2(ull v) {
    unsigned lo, hi;
    asm("mov.b64 {%0, %1}, %2;" : "=r"(lo), "=r"(hi) : "l"(v));
    return make_float2(__uint_as_float(lo), __uint_as_float(hi));
}

__device__ __forceinline__ float block_sum(float v, float* sm) {
    int t = threadIdx.x;
    sm[t] = v;
    __syncthreads();
    for (int s = blockDim.x >> 1; s > 0; s >>= 1) {
        if (t < s) sm[t] += sm[t + s];
        __syncthreads();
    }
    return sm[0];
}

// ===========================================================================
// K1: priors = x @ W  (per (c,r): [8,64] = [8,64]x[64,64]), fused s0 = mean_r
// grid: 2048 blocks (c * 64 r-blocks of 32 r), 256 threads, 72KB dyn smem
// thread = (o = t&63, rs = t>>6): 4 r-tiles in flight, 8 batches as 4 f32x2
// ===========================================================================
__global__ void __launch_bounds__(256) k_priors(const float* __restrict__ x,
                                                const float* __restrict__ W) {
    extern __shared__ float smem[];
    float* Ws = smem;              // 16384 floats: W for 4 r (rs*4096 + i*64 + o)
    float* xs = smem + 16384;      // 2048 floats: packed x2[(rs*4+q)*64+i] = {x[2q],x[2q+1]}

    const int t  = threadIdx.x;
    const int c  = blockIdx.x >> 6;
    const int rb = blockIdx.x & 63;
    const int o  = t & 63;
    const int rs = t >> 6;

    float s0[8] = {0,0,0,0,0,0,0,0};

    for (int g = 0; g < 8; g++) {
        const int r0 = rb * 32 + g * 4;
        __syncthreads();   // protect smem from previous iteration's readers

        // load W tile: 16384 contiguous floats
        {
            const float4* Wg = (const float4*)(W + ((size_t)(c * RR + r0) << 12));
            float4* Ws4 = (float4*)Ws;
            #pragma unroll
            for (int k = 0; k < 16; k++) Ws4[t + 256 * k] = Wg[t + 256 * k];
        }
        // load x, packed by batch pairs
        #pragma unroll
        for (int k = 0; k < 2; k++) {
            int lin = t + 256 * k;              // float4 id in [0,512)
            int b   = lin >> 6;
            int rem = lin & 63;
            int rl  = rem >> 4;                 // r within group
            int i4  = rem & 15;
            float4 xv = *(const float4*)(x + (((size_t)(b * CC + c) * RR + r0 + rl) << 6) + i4 * 4);
            float vals[4] = {xv.x, xv.y, xv.z, xv.w};
            #pragma unroll
            for (int e = 0; e < 4; e++) {
                int i = i4 * 4 + e;
                xs[((((rl * 4 + (b >> 1)) << 6) + i) << 1) + (b & 1)] = vals[e];
            }
        }
        __syncthreads();

        ull acc[4] = {0ull, 0ull, 0ull, 0ull};
        const float* Wrow = Ws + rs * 4096 + o;
        const ull*   x2   = ((const ull*)xs) + rs * 256;

        #pragma unroll 8
        for (int i = 0; i < 64; i += 2) {
            float w0 = Wrow[i * 64];
            float w1 = Wrow[(i + 1) * 64];
            ull w02 = pack2(w0, w0);
            ull w12 = pack2(w1, w1);
            #pragma unroll
            for (int q = 0; q < 4; q++) {
                ulonglong2 xv = *(const ulonglong2*)(x2 + q * 64 + i);
                acc[q] = fma2(w02, xv.x, acc[q]);
                acc[q] = fma2(w12, xv.y, acc[q]);
            }
        }

        const int r = r0 + rs;
        #pragma unroll
        for (int q = 0; q < 4; q++) {
            float2 a = unpack2(acc[q]);
            int b0 = 2 * q;
            g_priors[(((b0       * CC + c) * RR + r) << 6) + o] = a.x;
            g_priors[((((b0 + 1) * CC + c) * RR + r) << 6) + o] = a.y;
            s0[2 * q]     += a.x;
            s0[2 * q + 1] += a.y;
        }
    }

    // reduce s0 over rs (4 lanes) in smem, then global RED
    __syncthreads();
    #pragma unroll
    for (int q = 0; q < 8; q++) smem[rs * 512 + q * 64 + o] = s0[q];
    __syncthreads();
    #pragma unroll
    for (int k = 0; k < 2; k++) {
        int idx = t + 256 * k;                 // = b*64 + o
        float v = smem[idx] + smem[512 + idx] + smem[1024 + idx] + smem[1536 + idx];
        int b = idx >> 6, oo = idx & 63;
        atomicAdd(&g_s[(b * CC + c) * 64 + oo], v * (1.0f / RR));
    }
}

// ===========================================================================
// K3: one routing pass. block = (chunk ch, capsule bc). Stage 64KB tile in
// smem, pass 1: per-(o) max of logit = p*V[o]; pass 2: exp-weighted sums.
// ===========================================================================
__global__ void __launch_bounds__(256) k_route() {
    extern __shared__ float tile[];            // 16384 floats
    const int ch = blockIdx.x;
    const int bc = blockIdx.y;
    const int t  = threadIdx.x;
    const int o  = t & 63;
    const int rs = t >> 6;

    {
        const float4* src = (const float4*)(g_priors + (size_t)bc * RR * OO + (size_t)ch * CHR * OO);
        float4* t4 = (float4*)tile;
        #pragma unroll
        for (int k = 0; k < 16; k++) t4[t + 256 * k] = src[t + 256 * k];
    }
    const float V = g_V[bc * 64 + o];
    __syncthreads();

    const float* base = tile + (rs << 12) + o;   // rs*64*64 + o

    float m = -3.4e38f;
    #pragma unroll 8
    for (int j = 0; j < 64; j++) m = fmaxf(m, base[j * 64] * V);

    float l = 0.f, wa = 0.f;
    #pragma unroll 8
    for (int j = 0; j < 64; j++) {
        float p = base[j * 64];
        float e = __expf(p * V - m);
        l  += e;
        wa += e * p;
    }
    __syncthreads();     // tile free now
    tile[t] = m; tile[256 + t] = l; tile[512 + t] = wa;
    __syncthreads();

    if (t < 64) {
        float m0 = tile[t], m1 = tile[64 + t], m2 = tile[128 + t], m3 = tile[192 + t];
        float mm = fmaxf(fmaxf(m0, m1), fmaxf(m2, m3));
        float e0 = __expf(m0 - mm), e1 = __expf(m1 - mm);
        float e2 = __expf(m2 - mm), e3 = __expf(m3 - mm);
        float L  = tile[256 + t] * e0 + tile[320 + t] * e1 + tile[384 + t] * e2 + tile[448 + t] * e3;
        float Wt = tile[512 + t] * e0 + tile[576 + t] * e1 + tile[640 + t] * e2 + tile[704 + t] * e3;
        int idx = (bc * NCH + ch) * 64 + t;
        g_pm[idx] = mm; g_pl[idx] = L; g_pw[idx] = Wt;
    }
}

// K4: merge NCH chunk partials -> s, accumulate n2[slot]
__global__ void __launch_bounds__(256) k_merge(int slot) {
    __shared__ float red[256];
    const int idx = blockIdx.x * 256 + threadIdx.x;   // bc*64 + o
    const int bc = idx >> 6, o = idx & 63;

    float ms[NCH];
    float m = -3.4e38f;
    #pragma unroll
    for (int ch = 0; ch < NCH; ch++) {
        ms[ch] = g_pm[(bc * NCH + ch) * 64 + o];
        m = fmaxf(m, ms[ch]);
    }
    float L = 0.f, Wt = 0.f;
    #pragma unroll
    for (int ch = 0; ch < NCH; ch++) {
        float e = __expf(ms[ch] - m);
        L  += g_pl[(bc * NCH + ch) * 64 + o] * e;
        Wt += g_pw[(bc * NCH + ch) * 64 + o] * e;
    }
    float s = Wt / L;
    g_s[idx] = s;
    float r = block_sum(s * s, red);
    if (threadIdx.x == 0) atomicAdd(&g_n2[slot], r);
}

// Kn2: n2[0] from g_s (iteration 0 s comes from K1's fused mean)
__global__ void __launch_bounds__(512) k_n2_from_s() {
    __shared__ float red[512];
    const int idx = blockIdx.x * 512 + threadIdx.x;
    float s = g_s[idx];
    float r = block_sum(s * s, red);
    if (threadIdx.x == 0) atomicAdd(&g_n2[0], r);
}

// K5: v = squash(s) = s * sqrt(n2)/(1+n2); update V; optionally emit output
__global__ void __launch_bounds__(512) k_squash(int slot, int first, float* __restrict__ out) {
    const int idx = blockIdx.x * 512 + threadIdx.x;
    float n2 = g_n2[slot];
    float coef = sqrtf(n2) / (1.0f + n2);
    float v = coef * g_s[idx];
    g_V[idx] = first ? v : (g_V[idx] + v);
    if (out) out[idx] = v;
}

// ===========================================================================
extern "C" void kernel_launch(void* const* d_in, const int* in_sizes, int n_in,
                              void* d_out, int out_size) {
    const float* x = (const float*)d_in[0];
    const float* W = (const float*)d_in[1];
    float* out = (float*)d_out;

    cudaFuncSetAttribute(k_priors, cudaFuncAttributeMaxDynamicSharedMemorySize, 73728);
    cudaFuncSetAttribute(k_route,  cudaFuncAttributeMaxDynamicSharedMemorySize, 65536);

    void *ps = nullptr, *pn = nullptr;
    cudaGetSymbolAddress(&ps, g_s);
    cudaGetSymbolAddress(&pn, g_n2);
    cudaMemsetAsync(ps, 0, BC * OO * sizeof(float));
    cudaMemsetAsync(pn, 0, 3 * sizeof(float));

    // priors + fused uniform-softmax s0
    k_priors<<<2048, 256, 73728>>>(x, W);
    k_n2_from_s<<<32, 512>>>();
    k_squash<<<32, 512>>>(0, 1, nullptr);            // v0 -> V

    // routing iterations 1 and 2 (logits_k = priors * V implicitly)
    for (int it = 1; it <= 2; it++) {
        k_route<<<dim3(NCH, BC), 256, 65536>>>();
        k_merge<<<64, 256>>>(it);
        k_squash<<<32, 512>>>(it, 0, (it == 2) ? out : nullptr);
    }
}

// round 17
// speedup vs baseline: 1.1781x; 1.1781x over previous
#include <cuda_runtime.h>
#include <cstdint>

#define BB 8
#define CC 32
#define RR 2048
#define II 64
#define OO 64
#define BC (BB*CC)            // 256
#define NCH 8
#define CHR (RR/NCH)          // 256

typedef unsigned long long ull;

// -------- scratch (no allocations allowed -> __device__ globals) ----------
__device__ float g_priors[BB*CC*RR*OO];     // 128 MiB
__device__ float g_s[BC*OO];
__device__ float g_V[BC*OO];
__device__ float g_l[2][BC*OO];             // softmax denom accum per route pass
__device__ float g_w[2][BC*OO];             // weighted sum accum per route pass
__device__ float g_n2[3];

// -------- packed f32x2 helpers ----------
__device__ __forceinline__ ull pack2(float a, float b) {
    ull r;
    asm("mov.b64 %0, {%1, %2};" : "=l"(r)
        : "r"(__float_as_uint(a)), "r"(__float_as_uint(b)));
    return r;
}
__device__ __forceinline__ ull fma2(ull a, ull b, ull c) {
    ull d;
    asm("fma.rn.f32x2 %0, %1, %2, %3;" : "=l"(d) : "l"(a), "l"(b), "l"(c));
    return d;
}
__device__ __forceinline__ float2 unpack2(ull v) {
    unsigned lo, hi;
    asm("mov.b64 {%0, %1}, %2;" : "=r"(lo), "=r"(hi) : "l"(v));
    return make_float2(__uint_as_float(lo), __uint_as_float(hi));
}

__device__ __forceinline__ float block_sum(float v, float* sm) {
    int t = threadIdx.x;
    sm[t] = v;
    __syncthreads();
    for (int s = blockDim.x >> 1; s > 0; s >>= 1) {
        if (t < s) sm[t] += sm[t + s];
        __syncthreads();
    }
    return sm[0];
}

// ===========================================================================
// K1 v2: priors = x @ W, fused s0 = mean_r.
// W has NO intra-block reuse -> direct coalesced LDG (streaming), no W smem.
// Only x (64x reuse across o) goes through smem (8KB/iter). 16KB static smem
// -> 8 blocks/SM; W LDGs live inside the FFMA2 loop so unrolling gives MLP.
// grid: 2048 (c * 64 rb), 256 thr, thread=(o=t&63, rs=t>>6)
// ===========================================================================
__global__ void __launch_bounds__(256) k_priors(const float* __restrict__ x,
                                                const float* __restrict__ W) {
    __shared__ float xs[2048];     // packed pairs: [(rs*4+q)*64+i]*2 = {x[b=2q],x[b=2q+1]}
    __shared__ float red[2048];

    const int t  = threadIdx.x;
    const int c  = blockIdx.x >> 6;
    const int rb = blockIdx.x & 63;
    const int o  = t & 63;
    const int rs = t >> 6;

    float s0[8] = {0,0,0,0,0,0,0,0};

    for (int g = 0; g < 8; g++) {
        const int r0 = rb * 32 + g * 4;
        __syncthreads();

        // stage x for 4 r's, packed by batch pairs (2 float4 per thread)
        #pragma unroll
        for (int k = 0; k < 2; k++) {
            int lin = t + 256 * k;              // float4 id in [0,512)
            int b   = lin >> 6;
            int rem = lin & 63;
            int rl  = rem >> 4;
            int i4  = rem & 15;
            float4 xv = __ldcs((const float4*)(x + (((size_t)(b * CC + c) * RR + r0 + rl) << 6) + i4 * 4));
            float vals[4] = {xv.x, xv.y, xv.z, xv.w};
            #pragma unroll
            for (int e = 0; e < 4; e++) {
                int i = i4 * 4 + e;
                xs[((((rl * 4 + (b >> 1)) << 6) + i) << 1) + (b & 1)] = vals[e];
            }
        }
        __syncthreads();

        ull acc[4] = {0ull, 0ull, 0ull, 0ull};
        const float* Wp = W + ((size_t)(c * RR + r0 + rs) << 12) + o;  // W[c, r, i, o], i-stride 64
        const ull*   x2 = ((const ull*)xs) + rs * 256;

        #pragma unroll 8
        for (int i = 0; i < 64; i += 2) {
            float w0 = __ldcs(Wp + (i << 6));
            float w1 = __ldcs(Wp + ((i + 1) << 6));
            ull w02 = pack2(w0, w0);
            ull w12 = pack2(w1, w1);
            #pragma unroll
            for (int q = 0; q < 4; q++) {
                ulonglong2 xv = *(const ulonglong2*)(x2 + q * 64 + i);
                acc[q] = fma2(w02, xv.x, acc[q]);
                acc[q] = fma2(w12, xv.y, acc[q]);
            }
        }

        const int r = r0 + rs;
        #pragma unroll
        for (int q = 0; q < 4; q++) {
            float2 a = unpack2(acc[q]);
            int b0 = 2 * q;
            g_priors[(((size_t)(b0       * CC + c) * RR + r) << 6) + o] = a.x;
            g_priors[(((size_t)((b0 + 1) * CC + c) * RR + r) << 6) + o] = a.y;
            s0[2 * q]     += a.x;
            s0[2 * q + 1] += a.y;
        }
    }

    // reduce s0 over rs lanes in smem, then global RED (scaled to mean)
    __syncthreads();
    #pragma unroll
    for (int q = 0; q < 8; q++) red[rs * 512 + q * 64 + o] = s0[q];
    __syncthreads();
    #pragma unroll
    for (int k = 0; k < 2; k++) {
        int idx = t + 256 * k;                 // = b*64 + oo
        float v = red[idx] + red[512 + idx] + red[1024 + idx] + red[1536 + idx];
        int b = idx >> 6, oo = idx & 63;
        atomicAdd(&g_s[(b * CC + c) * 64 + oo], v * (1.0f / RR));
    }
}

// ===========================================================================
// K3 v2: single-pass routing (no max subtraction: |p*V| << 80 by construction
// -- squash coef ~0.04 keeps V tiny). No smem tile: stream priors straight
// from global with coalesced LDG, accumulate sum(e) and sum(e*p) per o,
// merge 4 rs-lanes in smem, atomically accumulate per (bc,o).
// grid: (NCH, BC), 256 thr
// ===========================================================================
__global__ void __launch_bounds__(256) k_route(int buf) {
    __shared__ float sl[256], sw[256];
    const int ch = blockIdx.x;
    const int bc = blockIdx.y;
    const int t  = threadIdx.x;
    const int o  = t & 63;
    const int rs = t >> 6;

    const float V = g_V[bc * 64 + o];
    const float* p = g_priors + (((size_t)bc * RR + ch * CHR + rs) << 6) + o;

    float l = 0.f, wa = 0.f;
    #pragma unroll 8
    for (int j = 0; j < 64; j++) {
        float pv = p[(size_t)j * 256];          // r = ch*CHR + 4j + rs
        float e = __expf(pv * V);
        l  += e;
        wa += e * pv;
    }
    sl[t] = l; sw[t] = wa;
    __syncthreads();
    if (t < 64) {
        float L  = sl[t] + sl[64 + t] + sl[128 + t] + sl[192 + t];
        float Wt = sw[t] + sw[64 + t] + sw[128 + t] + sw[192 + t];
        atomicAdd(&g_l[buf][bc * 64 + t], L);
        atomicAdd(&g_w[buf][bc * 64 + t], Wt);
    }
}

// K4: s = Wt/L per element, accumulate n2[slot]
__global__ void __launch_bounds__(256) k_finish(int buf, int slot) {
    __shared__ float red[256];
    const int idx = blockIdx.x * 256 + threadIdx.x;   // bc*64 + o
    float s = g_w[buf][idx] / g_l[buf][idx];
    g_s[idx] = s;
    float r = block_sum(s * s, red);
    if (threadIdx.x == 0) atomicAdd(&g_n2[slot], r);
}

// n2[0] from g_s (iteration-0 s comes from K1's fused mean)
__global__ void __launch_bounds__(512) k_n2_from_s() {
    __shared__ float red[512];
    const int idx = blockIdx.x * 512 + threadIdx.x;
    float s = g_s[idx];
    float r = block_sum(s * s, red);
    if (threadIdx.x == 0) atomicAdd(&g_n2[0], r);
}

// v = squash(s); update V; optionally emit output
__global__ void __launch_bounds__(512) k_squash(int slot, int first, float* __restrict__ out) {
    const int idx = blockIdx.x * 512 + threadIdx.x;
    float n2 = g_n2[slot];
    float coef = sqrtf(n2) / (1.0f + n2);
    float v = coef * g_s[idx];
    g_V[idx] = first ? v : (g_V[idx] + v);
    if (out) out[idx] = v;
}

// ===========================================================================
extern "C" void kernel_launch(void* const* d_in, const int* in_sizes, int n_in,
                              void* d_out, int out_size) {
    const float* x = (const float*)d_in[0];
    const float* W = (const float*)d_in[1];
    float* out = (float*)d_out;

    void *ps = nullptr, *pn = nullptr, *pl = nullptr, *pw = nullptr;
    cudaGetSymbolAddress(&ps, g_s);
    cudaGetSymbolAddress(&pn, g_n2);
    cudaGetSymbolAddress(&pl, g_l);
    cudaGetSymbolAddress(&pw, g_w);
    cudaMemsetAsync(ps, 0, BC * OO * sizeof(float));
    cudaMemsetAsync(pn, 0, 3 * sizeof(float));
    cudaMemsetAsync(pl, 0, 2 * BC * OO * sizeof(float));
    cudaMemsetAsync(pw, 0, 2 * BC * OO * sizeof(float));

    // priors + fused uniform-softmax s0
    k_priors<<<2048, 256>>>(x, W);
    k_n2_from_s<<<32, 512>>>();
    k_squash<<<32, 512>>>(0, 1, nullptr);            // v0 -> V

    // routing iterations 1 and 2 (logits_k = priors * V implicitly)
    for (int it = 1; it <= 2; it++) {
        int buf = it - 1;
        k_route<<<dim3(NCH, BC), 256>>>(buf);
        k_finish<<<64, 256>>>(buf, it);
        k_squash<<<32, 512>>>(it, 0, (it == 2) ? out : nullptr);
    }
}